// round 5
// baseline (speedup 1.0000x reference)
#include <cuda_runtime.h>
#include <cuda_bf16.h>

#define NPAIR 1024
#define NN 128
#define CC 64
#define NDIAG 255
#define DS 131                       // word stride: conflict-free with lane-permuted rows

#define INFV 1e30f
#define LOG2E 1.4426950408889634f
#define LN2f  0.6931471805599453f

#define SMEM_BYTES (NN * DS * 4)     // 67072 B: D fp32, aliased over GEMM staging

__device__ float g_bl[NPAIR];

__device__ __forceinline__ float ex2f(float x) {
    float r; asm("ex2.approx.ftz.f32 %0, %1;" : "=f"(r) : "f"(x)); return r;
}
__device__ __forceinline__ float lg2f(float x) {
    float r; asm("lg2.approx.ftz.f32 %0, %1;" : "=f"(r) : "f"(x)); return r;
}

// row i -> smem slot: lane-permuted so lane t reads rows 4t..4t+3 conflict-free
__device__ __forceinline__ int rowslot(int i) { return (i & 3) * 32 + (i >> 2); }

// ---------------- Fused: GEMM -> smem D (fp32) -> warp-synchronous DP ----------------
__global__ void __launch_bounds__(256, 2) dtw_fused_kernel(const float* __restrict__ x,
                                                           const float* __restrict__ y) {
    extern __shared__ float sm[];        // [NN*DS] D; first 33792B aliased as staging
    __shared__ float sx2[NN];
    __shared__ float sy2[NN];

    float* xs = sm;                      // [32][132]
    float* ys = sm + 32 * 132;           // [32][132]

    const int p   = blockIdx.x;
    const int tid = threadIdx.x;
    const float* __restrict__ xb = x + (size_t)p * NN * CC;
    const float* __restrict__ yb = y + (size_t)p * NN * CC;

    const int tm = tid >> 4;
    const int tn = tid & 15;
    const int i0 = tm * 8;
    const int j0 = tn * 8;

    float c[8][8];
#pragma unroll
    for (int m = 0; m < 8; m++)
#pragma unroll
        for (int n = 0; n < 8; n++) c[m][n] = 0.f;

    float accx = 0.f, accy = 0.f;

    for (int kc = 0; kc < 2; kc++) {
        __syncthreads();
        const int kbase = kc * 32;
        for (int t = tid; t < 128 * 32; t += 256) {
            int i  = t >> 5;
            int kk = t & 31;
            xs[kk * 132 + i] = xb[i * CC + kbase + kk];
            ys[kk * 132 + i] = yb[i * CC + kbase + kk];
        }
        __syncthreads();

        if (tid < 128) {
#pragma unroll 8
            for (int kk = 0; kk < 32; kk++) { float v = xs[kk * 132 + tid]; accx += v * v; }
        } else {
            int ii = tid - 128;
#pragma unroll 8
            for (int kk = 0; kk < 32; kk++) { float v = ys[kk * 132 + ii]; accy += v * v; }
        }

#pragma unroll 4
        for (int kk = 0; kk < 32; kk++) {
            float4 a0 = *(const float4*)&xs[kk * 132 + i0];
            float4 a1 = *(const float4*)&xs[kk * 132 + i0 + 4];
            float4 b0 = *(const float4*)&ys[kk * 132 + j0];
            float4 b1 = *(const float4*)&ys[kk * 132 + j0 + 4];
            float a[8] = {a0.x, a0.y, a0.z, a0.w, a1.x, a1.y, a1.z, a1.w};
            float b[8] = {b0.x, b0.y, b0.z, b0.w, b1.x, b1.y, b1.z, b1.w};
#pragma unroll
            for (int m = 0; m < 8; m++)
#pragma unroll
                for (int n = 0; n < 8; n++)
                    c[m][n] = fmaf(a[m], b[n], c[m][n]);
        }
    }

    __syncthreads();
    if (tid < 128) sx2[tid] = accx; else sy2[tid - 128] = accy;
    __syncthreads();                      // staging dead; sx2/sy2 visible

    // epilogue: D fp32 (base-2 prescaled) into lane-permuted smem layout
#pragma unroll
    for (int m = 0; m < 8; m++) {
        int srow = rowslot(i0 + m) * DS;
        float xx = sx2[i0 + m];
#pragma unroll
        for (int n = 0; n < 8; n++)
            sm[srow + j0 + n] = (xx + sy2[j0 + n] - 2.f * c[m][n]) * LOG2E;
    }
    __syncthreads();

    if (tid >= 32) return;                // warp 0 runs the DP alone, warp-synchronous
    const int lane = tid;

    float r1[4], r2[4];                   // R on diagonals d-1, d-2 for rows 4*lane+k
#pragma unroll
    for (int k = 0; k < 4; k++) { r1[k] = INFV; r2[k] = INFV; }

    const int base0 = (0 * 32 + lane) * DS - (4 * lane + 0);  // slot(4t+k)*DS - i
    const int base1 = (1 * 32 + lane) * DS - (4 * lane + 1);
    const int base2 = (2 * 32 + lane) * DS - (4 * lane + 2);
    const int base3 = (3 * 32 + lane) * DS - (4 * lane + 3);

    for (int d = 0; d < NDIAG; d++) {
        // boundary values from lane-1's last row (row 4t-1)
        float upB = __shfl_up_sync(0xffffffffu, r1[3], 1);
        float dgB = __shfl_up_sync(0xffffffffu, r2[3], 1);
        if (lane == 0) { upB = INFV; dgB = (d == 0) ? 0.f : INFV; }

        const int i_first = 4 * lane;
        float nw[4];
#pragma unroll
        for (int k = 0; k < 4; k++) {
            int i = i_first + k;
            int j = d - i;
            bool valid = (unsigned)j < (unsigned)NN;
            float dval = 0.f;
            if (valid) {
                int addr = (k == 0 ? base0 : k == 1 ? base1 : k == 2 ? base2 : base3) + d;
                dval = sm[addr];
            }
            float up = (k == 0) ? upB : r1[k - 1];
            float dg = (k == 0) ? dgB : r2[k - 1];
            float lf = r1[k];

            float mn  = fminf(lf, fminf(up, dg));
            float mx  = fmaxf(lf, fmaxf(up, dg));
            float md  = fmaxf(fminf(lf, up), fminf(fmaxf(lf, up), dg));
            float s   = 1.f + ex2f(mn - md) + ex2f(mn - mx);
            float r   = dval + mn - lg2f(s);
            nw[k] = valid ? r : INFV;
        }
#pragma unroll
        for (int k = 0; k < 4; k++) { r2[k] = r1[k]; r1[k] = nw[k]; }
    }

    if (lane == 31) g_bl[p] = r1[3] * LN2f;   // R[127][127], back to nat-log units
}

// ---------------- deterministic batch reduction ----------------
__global__ void dtw_reduce_kernel(float* __restrict__ out) {
    int b = threadIdx.x;
    if (b < 32) {
        float s = 0.f;
#pragma unroll
        for (int k = 0; k < 32; k++) s += g_bl[b * 32 + k];
        out[b] = s;
    }
}

extern "C" void kernel_launch(void* const* d_in, const int* in_sizes, int n_in,
                              void* d_out, int out_size) {
    (void)in_sizes; (void)n_in; (void)out_size;
    const float* x  = (const float*)d_in[0];
    const float* xr = (const float*)d_in[1];
    cudaFuncSetAttribute(dtw_fused_kernel, cudaFuncAttributeMaxDynamicSharedMemorySize, SMEM_BYTES);
    dtw_fused_kernel<<<NPAIR, 256, SMEM_BYTES>>>(x, xr);
    dtw_reduce_kernel<<<1, 32>>>((float*)d_out);
}